// round 4
// baseline (speedup 1.0000x reference)
#include <cuda_runtime.h>
#include <cstdint>

// Problem constants
#define BB   64
#define TT   2048
#define II   200
#define HH   100
#define G4   400   // 4*H

// Scratch: xg[t][b][j] (t-major so scan CTA b streams coalesced rows), ~210MB.
__device__ float g_xg[(size_t)TT * BB * G4];
// Transposed W_ih: Wt[k][j] = W_ih[j][k]  (200 x 400) for coalesced loads.
__device__ float g_Wt[II * G4];

// ---- packed fp32x2 FMA (FFMA2) ----------------------------------------
union f2u { float2 f; unsigned long long u; };
union f4u { float4 f; ulonglong2 u; };

__device__ __forceinline__ unsigned long long ffma2(unsigned long long a,
                                                    unsigned long long b,
                                                    unsigned long long c) {
    unsigned long long d;
    asm("fma.rn.f32x2 %0, %1, %2, %3;" : "=l"(d) : "l"(a), "l"(b), "l"(c));
    return d;
}

__device__ __forceinline__ float tanh_(float x) {
    return __fdividef(2.0f, 1.0f + __expf(-2.0f * x)) - 1.0f;
}

// ---- kernel 0: transpose W_ih ------------------------------------------
__global__ void transpose_wih(const float* __restrict__ Wih) {
    int o = blockIdx.x * 256 + threadIdx.x;   // o = k*400 + j (coalesced write)
    if (o < II * G4) {
        int k = o / G4;
        int j = o - k * G4;
        g_Wt[o] = Wih[j * II + k];
    }
}

// ---- kernel 1: input projection (register-blocked SIMT GEMM) -----------
// C[131072, 400] = x[131072, 200] @ Wt[200, 400]  (+bias), stored to g_xg
// CTA tile: 64 rows x 400 cols, K chunked by 20. Thread tile: 8x8.
#define KC 20
#define AS_STRIDE 72   // padded row stride for As (72*4=288B, 16B aligned)

__global__ __launch_bounds__(400, 1)
void proj_kernel(const float* __restrict__ x,
                 const float* __restrict__ bih,
                 const float* __restrict__ bhh) {
    __shared__ float As[KC * AS_STRIDE];   // As[k][r], 5.76 KB
    __shared__ float Bs[KC * G4];          // Bs[k][j], 32 KB

    const int tid  = threadIdx.x;
    const int tx   = tid % 50;             // column block: cols tx*8 .. tx*8+7
    const int ty   = tid / 50;             // row block:    rows ty*8 .. ty*8+7
    const int row0 = blockIdx.x * 64;

    unsigned long long acc[8][4];
    #pragma unroll
    for (int r = 0; r < 8; ++r)
        #pragma unroll
        for (int p = 0; p < 4; ++p) acc[r][p] = 0ULL;

    for (int cch = 0; cch < II / KC; ++cch) {
        const int k0 = cch * KC;
        __syncthreads();   // previous chunk fully consumed

        // Stage A: 64 rows x 20 k, transposed to As[k][r]
        if (tid < 320) {
            int r = tid & 63;
            int q = tid >> 6;              // 0..4 -> k-subgroup of 4
            float4 v = *(const float4*)&x[(size_t)(row0 + r) * II + k0 + 4 * q];
            As[(4 * q + 0) * AS_STRIDE + r] = v.x;
            As[(4 * q + 1) * AS_STRIDE + r] = v.y;
            As[(4 * q + 2) * AS_STRIDE + r] = v.z;
            As[(4 * q + 3) * AS_STRIDE + r] = v.w;
        }
        // Stage B: 20 x 400 floats = 2000 float4, coalesced
        for (int e = tid; e < KC * G4 / 4; e += 400) {
            int k = e / 100, p = e - k * 100;
            *(float4*)&Bs[k * G4 + 4 * p] =
                *(const float4*)&g_Wt[(size_t)(k0 + k) * G4 + 4 * p];
        }
        __syncthreads();

        #pragma unroll 2
        for (int k = 0; k < KC; ++k) {
            f4u a0, a1, w0, w1;
            a0.f = *(const float4*)&As[k * AS_STRIDE + ty * 8];
            a1.f = *(const float4*)&As[k * AS_STRIDE + ty * 8 + 4];
            w0.f = *(const float4*)&Bs[k * G4 + tx * 8];
            w1.f = *(const float4*)&Bs[k * G4 + tx * 8 + 4];
            float ar[8] = {a0.f.x, a0.f.y, a0.f.z, a0.f.w,
                           a1.f.x, a1.f.y, a1.f.z, a1.f.w};
            #pragma unroll
            for (int r = 0; r < 8; ++r) {
                f2u av; av.f.x = ar[r]; av.f.y = ar[r];
                acc[r][0] = ffma2(av.u, w0.u.x, acc[r][0]);
                acc[r][1] = ffma2(av.u, w0.u.y, acc[r][1]);
                acc[r][2] = ffma2(av.u, w1.u.x, acc[r][2]);
                acc[r][3] = ffma2(av.u, w1.u.y, acc[r][3]);
            }
        }
    }

    // Epilogue: add bias, scatter rows to g_xg[t][b][col]
    f4u bi0, bi1, bh0, bh1;
    bi0.f = *(const float4*)&bih[tx * 8];
    bi1.f = *(const float4*)&bih[tx * 8 + 4];
    bh0.f = *(const float4*)&bhh[tx * 8];
    bh1.f = *(const float4*)&bhh[tx * 8 + 4];
    float bias[8] = {bi0.f.x + bh0.f.x, bi0.f.y + bh0.f.y,
                     bi0.f.z + bh0.f.z, bi0.f.w + bh0.f.w,
                     bi1.f.x + bh1.f.x, bi1.f.y + bh1.f.y,
                     bi1.f.z + bh1.f.z, bi1.f.w + bh1.f.w};

    #pragma unroll
    for (int r = 0; r < 8; ++r) {
        int m = row0 + ty * 8 + r;
        int b = m >> 11;           // m / 2048
        int t = m & 2047;
        float* dst = &g_xg[((size_t)t * BB + b) * G4 + tx * 8];
        f2u p0, p1, p2, p3;
        p0.u = acc[r][0]; p1.u = acc[r][1]; p2.u = acc[r][2]; p3.u = acc[r][3];
        float4 o0 = make_float4(p0.f.x + bias[0], p0.f.y + bias[1],
                                p1.f.x + bias[2], p1.f.y + bias[3]);
        float4 o1 = make_float4(p2.f.x + bias[4], p2.f.y + bias[5],
                                p3.f.x + bias[6], p3.f.y + bias[7]);
        *(float4*)dst       = o0;
        *(float4*)(dst + 4) = o1;
    }
}

// ---- kernel 2: sequential LSTM scan ------------------------------------
// One CTA per batch row, 400 threads. Threads 4j..4j+3 own the i,f,g,o
// gates of hidden unit j (same quad) -> combine via quad shfl (no barrier).
// h is DOUBLE-BUFFERED: step t reads h_sh[p], writes h_sh[p^1], then one
// __syncthreads. The end-of-step barrier guarantees all step-t reads of
// h_sh[p] complete before any step-t+1 write to h_sh[p] -> race-free with
// a single barrier per step.
__global__ __launch_bounds__(400, 1)
void scan_kernel(const float* __restrict__ Whh, float* __restrict__ out) {
    const int b    = blockIdx.x;
    const int tid  = threadIdx.x;
    const int j    = tid >> 2;     // hidden unit 0..99
    const int g    = tid & 3;      // gate: 0=i 1=f 2=g 3=o
    const unsigned qmask = 0xFu << ((tid & 31) & ~3);   // this thread's quad

    __shared__ __align__(16) float h_sh[2][HH];   // 2 x 400B, both 16B aligned

    // W_hh row (g*100 + j), 100 floats -> 25 float4 in registers
    f4u wreg[HH / 4];
    const float4* wr = (const float4*)(Whh + (size_t)(g * HH + j) * HH);
    #pragma unroll
    for (int q = 0; q < HH / 4; ++q) wreg[q].f = wr[q];

    float c = 0.0f, hval = 0.0f;
    if (tid < HH) h_sh[0][tid] = 0.0f;
    __syncthreads();

    const float* xg = g_xg + (size_t)b * G4 + (g * HH + j);
    const size_t tstride = (size_t)BB * G4;
    float xv = xg[0];
    int p = 0;

    for (int t = 0; t < TT; ++t) {
        // prefetch next step's xg element (consumed next iteration)
        float xv_next = xg[(size_t)(t + 1 < TT ? t + 1 : TT - 1) * tstride];

        unsigned long long acc0 = 0ULL, acc1 = 0ULL;
        const float4* hb = (const float4*)h_sh[p];
        #pragma unroll
        for (int q = 0; q < HH / 4; ++q) {
            f4u h4; h4.f = hb[q];            // broadcast LDS.128
            acc0 = ffma2(wreg[q].u.x, h4.u.x, acc0);
            acc1 = ffma2(wreg[q].u.y, h4.u.y, acc1);
        }
        f2u s0, s1; s0.u = acc0; s1.u = acc1;
        float gate = s0.f.x + s0.f.y + s1.f.x + s1.f.y + xv;

        // branch-free activation: g==2 -> tanh = 2*sig(2x)-1, else sigmoid
        bool is_t = (g == 2);
        float xx = is_t ? 2.0f * gate : gate;
        float s  = __fdividef(1.0f, 1.0f + __expf(-xx));
        float a  = is_t ? fmaf(2.0f, s, -1.0f) : s;

        // quad combine (lanes of this quad, all converged)
        float fg = __shfl_down_sync(qmask, a, 1, 4);
        float gg = __shfl_down_sync(qmask, a, 2, 4);
        float og = __shfl_down_sync(qmask, a, 3, 4);
        if (g == 0) {
            c    = fg * c + a * gg;
            hval = og * tanh_(c);
            h_sh[p ^ 1][j] = hval;           // write OTHER buffer
        }
        __syncthreads();
        p ^= 1;
        xv = xv_next;
    }

    if (g == 0) out[b * HH + j] = hval;
}

// ---- launch ------------------------------------------------------------
extern "C" void kernel_launch(void* const* d_in, const int* in_sizes, int n_in,
                              void* d_out, int out_size) {
    const float* x   = (const float*)d_in[0];   // [64,2048,200]
    const float* Wih = (const float*)d_in[1];   // [400,200]
    const float* Whh = (const float*)d_in[2];   // [400,100]
    const float* bih = (const float*)d_in[3];   // [400]
    const float* bhh = (const float*)d_in[4];   // [400]
    float* out = (float*)d_out;                 // [64,100]

    transpose_wih<<<(II * G4 + 255) / 256, 256>>>(Wih);
    proj_kernel<<<TT * BB / 64, 400>>>(x, bih, bhh);
    scan_kernel<<<BB, 400>>>(Whh, out);
}

// round 5
// speedup vs baseline: 1.0321x; 1.0321x over previous
#include <cuda_runtime.h>
#include <cstdint>

// Problem constants
#define BB   64
#define TT   2048
#define II   200
#define HH   100
#define G4   400   // 4*H

// Scratch: xg[t][b][j] (t-major so scan CTA b streams coalesced rows), ~210MB.
__device__ float g_xg[(size_t)TT * BB * G4];

// ---- packed fp32x2 FMA (FFMA2) ----------------------------------------
union f2u { float2 f; unsigned long long u; };
union f4u { float4 f; ulonglong2 u; };

__device__ __forceinline__ unsigned long long ffma2(unsigned long long a,
                                                    unsigned long long b,
                                                    unsigned long long c) {
    unsigned long long d;
    asm("fma.rn.f32x2 %0, %1, %2, %3;" : "=l"(d) : "l"(a), "l"(b), "l"(c));
    return d;
}

__device__ __forceinline__ float tanh_(float x) {
    return __fdividef(2.0f, 1.0f + __expf(-2.0f * x)) - 1.0f;
}

// ---- kernel 1: input projection (register-blocked SIMT GEMM) -----------
// C[131072, 400] = x[131072, 200] @ W_ih^T  (+bias) -> g_xg[t][b][col]
// CTA tile: 64 rows x 100 cols (grid 2048 x 4). 200 threads, thread tile 8x4.
// K chunked by 20. W_ih transposed on the fly during B staging.
#define KC 20
#define AS_STRIDE 68   // 68*4=272B, 16B aligned

__global__ __launch_bounds__(200, 4)
void proj_kernel(const float* __restrict__ x,
                 const float* __restrict__ Wih,
                 const float* __restrict__ bih,
                 const float* __restrict__ bhh) {
    __shared__ float As[KC * AS_STRIDE];   // As[k][r], 5.44 KB
    __shared__ float Bs[KC * HH];          // Bs[k][jc], 8 KB

    const int tid  = threadIdx.x;
    const int tx   = tid % 25;             // col group: cols tx*4 .. tx*4+3
    const int ty   = tid / 25;             // row group: rows ty*8 .. ty*8+7
    const int row0 = blockIdx.x * 64;
    const int c0   = blockIdx.y * HH;      // global column base (0/100/200/300)

    unsigned long long acc[8][2];
    #pragma unroll
    for (int r = 0; r < 8; ++r) { acc[r][0] = 0ULL; acc[r][1] = 0ULL; }

    for (int cch = 0; cch < II / KC; ++cch) {
        const int k0 = cch * KC;
        __syncthreads();   // previous chunk fully consumed

        // Stage A: 64 rows x 20 k, transposed to As[k][r]. 320 float4 loads.
        for (int idx = tid; idx < 64 * (KC / 4); idx += 200) {
            int r = idx / (KC / 4);
            int q = idx - r * (KC / 4);
            float4 v = *(const float4*)&x[(size_t)(row0 + r) * II + k0 + 4 * q];
            As[(4 * q + 0) * AS_STRIDE + r] = v.x;
            As[(4 * q + 1) * AS_STRIDE + r] = v.y;
            As[(4 * q + 2) * AS_STRIDE + r] = v.z;
            As[(4 * q + 3) * AS_STRIDE + r] = v.w;
        }
        // Stage B (transposing): thread t<100 owns W_ih row j=c0+t,
        // reads 20 floats (5 float4, L2-resident), writes Bs[k][t].
        if (tid < HH) {
            const float* wrow = &Wih[(size_t)(c0 + tid) * II + k0];
            #pragma unroll
            for (int q = 0; q < KC / 4; ++q) {
                float4 v = *(const float4*)&wrow[4 * q];
                Bs[(4 * q + 0) * HH + tid] = v.x;
                Bs[(4 * q + 1) * HH + tid] = v.y;
                Bs[(4 * q + 2) * HH + tid] = v.z;
                Bs[(4 * q + 3) * HH + tid] = v.w;
            }
        }
        __syncthreads();

        #pragma unroll 4
        for (int k = 0; k < KC; ++k) {
            f4u a0, a1, w0;
            a0.f = *(const float4*)&As[k * AS_STRIDE + ty * 8];
            a1.f = *(const float4*)&As[k * AS_STRIDE + ty * 8 + 4];
            w0.f = *(const float4*)&Bs[k * HH + tx * 4];
            float ar[8] = {a0.f.x, a0.f.y, a0.f.z, a0.f.w,
                           a1.f.x, a1.f.y, a1.f.z, a1.f.w};
            #pragma unroll
            for (int r = 0; r < 8; ++r) {
                f2u av; av.f.x = ar[r]; av.f.y = ar[r];
                acc[r][0] = ffma2(av.u, w0.u.x, acc[r][0]);
                acc[r][1] = ffma2(av.u, w0.u.y, acc[r][1]);
            }
        }
    }

    // Epilogue: add bias, scatter rows to g_xg[t][b][col]
    const int col = c0 + tx * 4;
    f4u bi, bh;
    bi.f = *(const float4*)&bih[col];
    bh.f = *(const float4*)&bhh[col];
    float4 bias = make_float4(bi.f.x + bh.f.x, bi.f.y + bh.f.y,
                              bi.f.z + bh.f.z, bi.f.w + bh.f.w);

    #pragma unroll
    for (int r = 0; r < 8; ++r) {
        int m = row0 + ty * 8 + r;
        int b = m >> 11;           // m / 2048
        int t = m & 2047;
        f2u p0, p1;
        p0.u = acc[r][0]; p1.u = acc[r][1];
        float4 o = make_float4(p0.f.x + bias.x, p0.f.y + bias.y,
                               p1.f.x + bias.z, p1.f.y + bias.w);
        *(float4*)&g_xg[((size_t)t * BB + b) * G4 + col] = o;
    }
}

// ---- kernel 2: sequential LSTM scan ------------------------------------
// One CTA per batch row, 400 threads. Threads 4j..4j+3 own the i,f,g,o
// gates of hidden unit j (same quad) -> combine via quad shfl (no barrier).
// h double-buffered: step t reads h_sh[p], writes h_sh[p^1], one barrier.
__global__ __launch_bounds__(400, 1)
void scan_kernel(const float* __restrict__ Whh, float* __restrict__ out) {
    const int b    = blockIdx.x;
    const int tid  = threadIdx.x;
    const int j    = tid >> 2;     // hidden unit 0..99
    const int g    = tid & 3;      // gate: 0=i 1=f 2=g 3=o
    const unsigned qmask = 0xFu << ((tid & 31) & ~3);   // this thread's quad

    __shared__ __align__(16) float h_sh[2][HH];

    // W_hh row (g*100 + j), 100 floats -> 25 float4 in registers
    f4u wreg[HH / 4];
    const float4* wr = (const float4*)(Whh + (size_t)(g * HH + j) * HH);
    #pragma unroll
    for (int q = 0; q < HH / 4; ++q) wreg[q].f = wr[q];

    float c = 0.0f, hval = 0.0f;
    if (tid < HH) h_sh[0][tid] = 0.0f;
    __syncthreads();

    const float* xg = g_xg + (size_t)b * G4 + (g * HH + j);
    const size_t tstride = (size_t)BB * G4;
    float xv = xg[0];
    int p = 0;

    for (int t = 0; t < TT; ++t) {
        float xv_next = xg[(size_t)(t + 1 < TT ? t + 1 : TT - 1) * tstride];

        unsigned long long acc0 = 0ULL, acc1 = 0ULL;
        const float4* hb = (const float4*)h_sh[p];
        #pragma unroll
        for (int q = 0; q < HH / 4; ++q) {
            f4u h4; h4.f = hb[q];            // broadcast LDS.128
            acc0 = ffma2(wreg[q].u.x, h4.u.x, acc0);
            acc1 = ffma2(wreg[q].u.y, h4.u.y, acc1);
        }
        f2u s0, s1; s0.u = acc0; s1.u = acc1;
        float gate = s0.f.x + s0.f.y + s1.f.x + s1.f.y + xv;

        bool is_t = (g == 2);
        float xx = is_t ? 2.0f * gate : gate;
        float s  = __fdividef(1.0f, 1.0f + __expf(-xx));
        float a  = is_t ? fmaf(2.0f, s, -1.0f) : s;

        float fg = __shfl_down_sync(qmask, a, 1, 4);
        float gg = __shfl_down_sync(qmask, a, 2, 4);
        float og = __shfl_down_sync(qmask, a, 3, 4);
        if (g == 0) {
            c    = fg * c + a * gg;
            hval = og * tanh_(c);
            h_sh[p ^ 1][j] = hval;           // write OTHER buffer
        }
        __syncthreads();
        p ^= 1;
        xv = xv_next;
    }

    if (g == 0) out[b * HH + j] = hval;
}

// ---- launch ------------------------------------------------------------
extern "C" void kernel_launch(void* const* d_in, const int* in_sizes, int n_in,
                              void* d_out, int out_size) {
    const float* x   = (const float*)d_in[0];   // [64,2048,200]
    const float* Wih = (const float*)d_in[1];   // [400,200]
    const float* Whh = (const float*)d_in[2];   // [400,100]
    const float* bih = (const float*)d_in[3];   // [400]
    const float* bhh = (const float*)d_in[4];   // [400]
    float* out = (float*)d_out;                 // [64,100]

    proj_kernel<<<dim3(TT * BB / 64, 4), 200>>>(x, Wih, bih, bhh);
    scan_kernel<<<BB, 400>>>(Whh, out);
}

// round 6
// speedup vs baseline: 1.2315x; 1.1932x over previous
#include <cuda_runtime.h>
#include <cstdint>

// Problem constants
#define BB   64
#define TT   2048
#define II   200
#define HH   100
#define G4   400   // 4*H

// Scratch: xg[t][b][j] (t-major so scan CTA b streams coalesced rows), ~210MB.
__device__ float g_xg[(size_t)TT * BB * G4];

// ---- packed fp32x2 helpers ---------------------------------------------
union f2u { float2 f; unsigned long long u; };
union f4u { float4 f; ulonglong2 u; };

__device__ __forceinline__ unsigned long long ffma2(unsigned long long a,
                                                    unsigned long long b,
                                                    unsigned long long c) {
    unsigned long long d;
    asm("fma.rn.f32x2 %0, %1, %2, %3;" : "=l"(d) : "l"(a), "l"(b), "l"(c));
    return d;
}
__device__ __forceinline__ unsigned long long fadd2(unsigned long long a,
                                                    unsigned long long b) {
    unsigned long long d;
    asm("add.rn.f32x2 %0, %1, %2;" : "=l"(d) : "l"(a), "l"(b));
    return d;
}

__device__ __forceinline__ float tanh_(float x) {
    return __fdividef(2.0f, 1.0f + __expf(-2.0f * x)) - 1.0f;
}

// ---- kernel 1: input projection (register-blocked SIMT GEMM) -----------
// C[131072, 400] = x[131072, 200] @ W_ih^T  (+bias) -> g_xg[t][b][col]
// CTA tile: 64 rows x 100 cols (grid 2048 x 4). 200 threads, thread tile 8x4.
#define KC 20
#define AS_STRIDE 68   // 68*4=272B, 16B aligned

__global__ __launch_bounds__(200, 4)
void proj_kernel(const float* __restrict__ x,
                 const float* __restrict__ Wih,
                 const float* __restrict__ bih,
                 const float* __restrict__ bhh) {
    __shared__ float As[KC * AS_STRIDE];   // As[k][r], 5.44 KB
    __shared__ float Bs[KC * HH];          // Bs[k][jc], 8 KB

    const int tid  = threadIdx.x;
    const int tx   = tid % 25;             // col group: cols tx*4 .. tx*4+3
    const int ty   = tid / 25;             // row group: rows ty*8 .. ty*8+7
    const int row0 = blockIdx.x * 64;
    const int c0   = blockIdx.y * HH;      // global column base (0/100/200/300)

    unsigned long long acc[8][2];
    #pragma unroll
    for (int r = 0; r < 8; ++r) { acc[r][0] = 0ULL; acc[r][1] = 0ULL; }

    for (int cch = 0; cch < II / KC; ++cch) {
        const int k0 = cch * KC;
        __syncthreads();   // previous chunk fully consumed

        // Stage A: 64 rows x 20 k, transposed to As[k][r]. 320 float4 loads.
        for (int idx = tid; idx < 64 * (KC / 4); idx += 200) {
            int r = idx / (KC / 4);
            int q = idx - r * (KC / 4);
            float4 v = *(const float4*)&x[(size_t)(row0 + r) * II + k0 + 4 * q];
            As[(4 * q + 0) * AS_STRIDE + r] = v.x;
            As[(4 * q + 1) * AS_STRIDE + r] = v.y;
            As[(4 * q + 2) * AS_STRIDE + r] = v.z;
            As[(4 * q + 3) * AS_STRIDE + r] = v.w;
        }
        // Stage B (transposing): thread t<100 owns W_ih row j=c0+t (L2-resident)
        if (tid < HH) {
            const float* wrow = &Wih[(size_t)(c0 + tid) * II + k0];
            #pragma unroll
            for (int q = 0; q < KC / 4; ++q) {
                float4 v = *(const float4*)&wrow[4 * q];
                Bs[(4 * q + 0) * HH + tid] = v.x;
                Bs[(4 * q + 1) * HH + tid] = v.y;
                Bs[(4 * q + 2) * HH + tid] = v.z;
                Bs[(4 * q + 3) * HH + tid] = v.w;
            }
        }
        __syncthreads();

        #pragma unroll 4
        for (int k = 0; k < KC; ++k) {
            f4u a0, a1, w0;
            a0.f = *(const float4*)&As[k * AS_STRIDE + ty * 8];
            a1.f = *(const float4*)&As[k * AS_STRIDE + ty * 8 + 4];
            w0.f = *(const float4*)&Bs[k * HH + tx * 4];
            float ar[8] = {a0.f.x, a0.f.y, a0.f.z, a0.f.w,
                           a1.f.x, a1.f.y, a1.f.z, a1.f.w};
            #pragma unroll
            for (int r = 0; r < 8; ++r) {
                f2u av; av.f.x = ar[r]; av.f.y = ar[r];
                acc[r][0] = ffma2(av.u, w0.u.x, acc[r][0]);
                acc[r][1] = ffma2(av.u, w0.u.y, acc[r][1]);
            }
        }
    }

    // Epilogue: add bias, scatter rows to g_xg[t][b][col]
    const int col = c0 + tx * 4;
    f4u bi, bh;
    bi.f = *(const float4*)&bih[col];
    bh.f = *(const float4*)&bhh[col];
    float4 bias = make_float4(bi.f.x + bh.f.x, bi.f.y + bh.f.y,
                              bi.f.z + bh.f.z, bi.f.w + bh.f.w);

    #pragma unroll
    for (int r = 0; r < 8; ++r) {
        int m = row0 + ty * 8 + r;
        int b = m >> 11;           // m / 2048
        int t = m & 2047;
        f2u p0, p1;
        p0.u = acc[r][0]; p1.u = acc[r][1];
        float4 o = make_float4(p0.f.x + bias.x, p0.f.y + bias.y,
                               p1.f.x + bias.z, p1.f.y + bias.w);
        *(float4*)&g_xg[((size_t)t * BB + b) * G4 + col] = o;
    }
}

// ---- kernel 2: sequential LSTM scan ------------------------------------
// One CTA per batch row, 400 threads. Threads 4j..4j+3 own the i,f,g,o
// gates of hidden unit j (same quad) -> combine via quad shfl.
// h double-buffered (1 barrier/step). xg is prefetched a FULL GROUP (4
// steps, >2000 cyc) ahead via a register ring so DRAM latency never lands
// on the per-step critical path.
#define SG 4   // steps per prefetch group (TT % SG == 0)

__global__ __launch_bounds__(400, 1)
void scan_kernel(const float* __restrict__ Whh, float* __restrict__ out) {
    const int b    = blockIdx.x;
    const int tid  = threadIdx.x;
    const int j    = tid >> 2;     // hidden unit 0..99
    const int g    = tid & 3;      // gate: 0=i 1=f 2=g 3=o
    const unsigned qmask = 0xFu << ((tid & 31) & ~3);   // this thread's quad

    __shared__ __align__(16) float h_sh[2][HH];

    // W_hh row (g*100 + j), 100 floats -> 25 float4 in registers
    f4u wreg[HH / 4];
    const float4* wr = (const float4*)(Whh + (size_t)(g * HH + j) * HH);
    #pragma unroll
    for (int q = 0; q < HH / 4; ++q) wreg[q].f = wr[q];

    float c = 0.0f, hval = 0.0f;
    if (tid < HH) h_sh[0][tid] = 0.0f;
    __syncthreads();

    const float* xg = g_xg + (size_t)b * G4 + (g * HH + j);
    const size_t tstride = (size_t)BB * G4;

    float cur[SG], nxt[SG];
    #pragma unroll
    for (int i = 0; i < SG; ++i) cur[i] = __ldcs(&xg[(size_t)i * tstride]);

    int p = 0;
    for (int tg = 0; tg < TT; tg += SG) {
        // issue next group's loads NOW (consumed >= SG steps from now)
        #pragma unroll
        for (int i = 0; i < SG; ++i) {
            int tt = tg + SG + i;
            tt = (tt < TT) ? tt : (TT - 1);
            nxt[i] = __ldcs(&xg[(size_t)tt * tstride]);
        }

        #pragma unroll
        for (int i = 0; i < SG; ++i) {
            // 4 independent accumulation chains (depth ~13 each)
            unsigned long long a0 = 0ULL, a1 = 0ULL, a2 = 0ULL, a3 = 0ULL;
            const float4* hb = (const float4*)h_sh[p];
            #pragma unroll
            for (int q = 0; q < HH / 4; ++q) {
                f4u h4; h4.f = hb[q];            // broadcast LDS.128
                if (q & 1) {
                    a2 = ffma2(wreg[q].u.x, h4.u.x, a2);
                    a3 = ffma2(wreg[q].u.y, h4.u.y, a3);
                } else {
                    a0 = ffma2(wreg[q].u.x, h4.u.x, a0);
                    a1 = ffma2(wreg[q].u.y, h4.u.y, a1);
                }
            }
            f2u s0, s1;
            s0.u = fadd2(a0, a2);
            s1.u = fadd2(a1, a3);
            float gate = (s0.f.x + s0.f.y) + (s1.f.x + s1.f.y) + cur[i];

            // branch-free activation: g==2 -> tanh = 2*sig(2x)-1, else sigmoid
            bool is_t = (g == 2);
            float xx = is_t ? 2.0f * gate : gate;
            float s  = __fdividef(1.0f, 1.0f + __expf(-xx));
            float a  = is_t ? fmaf(2.0f, s, -1.0f) : s;

            // quad combine (lanes of this quad, all converged)
            float fg = __shfl_down_sync(qmask, a, 1, 4);
            float gg = __shfl_down_sync(qmask, a, 2, 4);
            float og = __shfl_down_sync(qmask, a, 3, 4);
            if (g == 0) {
                c    = fg * c + a * gg;
                hval = og * tanh_(c);
                h_sh[p ^ 1][j] = hval;           // write OTHER buffer
            }
            __syncthreads();
            p ^= 1;
        }

        #pragma unroll
        for (int i = 0; i < SG; ++i) cur[i] = nxt[i];
    }

    if (g == 0) out[b * HH + j] = hval;
}

// ---- launch ------------------------------------------------------------
extern "C" void kernel_launch(void* const* d_in, const int* in_sizes, int n_in,
                              void* d_out, int out_size) {
    const float* x   = (const float*)d_in[0];   // [64,2048,200]
    const float* Wih = (const float*)d_in[1];   // [400,200]
    const float* Whh = (const float*)d_in[2];   // [400,100]
    const float* bih = (const float*)d_in[3];   // [400]
    const float* bhh = (const float*)d_in[4];   // [400]
    float* out = (float*)d_out;                 // [64,100]

    proj_kernel<<<dim3(TT * BB / 64, 4), 200>>>(x, Wih, bih, bhh);
    scan_kernel<<<BB, 400>>>(Whh, out);
}